// round 2
// baseline (speedup 1.0000x reference)
#include <cuda_runtime.h>
#include <cstdint>

typedef unsigned long long ull;

#define THREADS 256
#define OUTF 11008
#define INF 4096
#define NBLK 688              /* OUTF/16 row-blocks, one per CTA */

#define SMEM_LUT_BYTES (512*16*8)   /* LUT replicated 16x, interleaved: 64KB */
#define SMEM_RED_BYTES (8*64*4)     /* cross-warp reduction: 2KB */
#define SMEM_TOTAL (SMEM_LUT_BYTES + SMEM_RED_BYTES)

__device__ __forceinline__ uint32_t smem_u32(const void* p) {
    uint32_t a;
    asm("{ .reg .u64 t; cvta.to.shared.u64 t, %1; cvt.u32.u64 %0, t; }"
        : "=r"(a) : "l"(p));
    return a;
}
__device__ __forceinline__ ull pack2(float lo, float hi) {
    ull r; asm("mov.b64 %0, {%1,%2};" : "=l"(r) : "f"(lo), "f"(hi)); return r;
}
__device__ __forceinline__ void fma2(ull& acc, ull a, ull b) {
    asm("fma.rn.f32x2 %0, %1, %2, %0;" : "+l"(acc) : "l"(a), "l"(b));
}
__device__ __forceinline__ float sum2(ull v) {
    float a, b; asm("mov.b64 {%0,%1}, %2;" : "=f"(a), "=f"(b) : "l"(v));
    return a + b;
}
__device__ __forceinline__ ull lds64(uint32_t addr) {
    ull v; asm("ld.shared.b64 %0, [%1];" : "=l"(v) : "r"(addr));
    return v;
}

__global__ void __launch_bounds__(THREADS, 1)
tcq_kernel(const float* __restrict__ inp,
           const int* __restrict__ trellis1,
           const int* __restrict__ trellis2,
           const float* __restrict__ tlut,
           float* __restrict__ out)
{
    extern __shared__ char smem_raw[];
    ull*   lut = (ull*)smem_raw;
    float* red = (float*)(smem_raw + SMEM_LUT_BYTES);

    const int tid  = threadIdx.x;
    const int lane = tid & 31;
    const int warp = tid >> 5;
    const int mo   = blockIdx.x;

    // ---- trellis for this thread's block: issue all 8 int4 loads early ----
    // thread tid<128 -> partition 1, ko=tid; else partition 2, ko=tid-128.
    const int4* tq = (tid < 128)
        ? (const int4*)(trellis1 + (size_t)(mo * 128 + tid) * 32)
        : (const int4*)(trellis2 + (size_t)(mo * 128 + (tid - 128)) * 32);
    int4 iwa[8];
#pragma unroll
    for (int q = 0; q < 8; q++) iwa[q] = tq[q];

    // ---- stage LUT replicated 16x interleaved: entry e, replica r at
    //      byte e*128 + r*8. Lane l reads replica l&15 -> bank = f(lane)
    //      only -> conflict-free LDS.64 for arbitrary random idx. ----
    {
        const ull* src = (const ull*)tlut;   // 512 float2 entries
        for (int k = tid; k < 512 * 16; k += THREADS)
            lut[k] = src[k >> 4];            // consecutive 8B stores: conflict-free
    }

    // ---- x for this thread's 16 global columns [tid*16, tid*16+16),
    //      packed as f32x2 pairs (pair j = cols 2j,2j+1), 4 batches ----
    ull x2[4][8];
    {
        const float4* xv = (const float4*)inp;
#pragma unroll
        for (int b = 0; b < 4; b++) {
#pragma unroll
            for (int q = 0; q < 4; q++) {
                float4 v = xv[b * (INF / 4) + tid * 4 + q];
                x2[b][2 * q + 0] = pack2(v.x, v.y);
                x2[b][2 * q + 1] = pack2(v.z, v.w);
            }
        }
    }

    __syncthreads();

    const uint32_t lut_lane = smem_u32(smem_raw) + (uint32_t)(lane & 15) * 8u;

    // Decode: idx[s] = 9-bit window ending at nibble s of the big-endian
    // 16-bit word stream (state recurrence collapses because L == 4*kv).
    uint32_t prev = 0;

#pragma unroll
    for (int p2 = 0; p2 < 2; p2++) {           // rows p2*8 .. p2*8+7
        uint32_t wd[16];
#pragma unroll
        for (int q = 0; q < 4; q++) {
            const int4 w4 = iwa[p2 * 4 + q];
            wd[4 * q + 0] = (uint32_t)w4.x; wd[4 * q + 1] = (uint32_t)w4.y;
            wd[4 * q + 2] = (uint32_t)w4.z; wd[4 * q + 3] = (uint32_t)w4.w;
        }

        ull acc[8][4];                          // [row-in-phase][batch] packed f32x2
#pragma unroll
        for (int t = 0; t < 8; t++)
#pragma unroll
            for (int b = 0; b < 4; b++) acc[t][b] = 0ull;

#pragma unroll
        for (int tx = 0; tx < 8; tx++) {        // row tx: words 2tx, 2tx+1
#pragma unroll
            for (int h = 0; h < 2; h++) {
                const uint32_t w   = wd[2 * tx + h] & 0xFFFFu;
                const uint32_t ctx = (prev << 16) | w;
                prev = w;
#pragma unroll
                for (int t = 0; t < 4; t++) {
                    const uint32_t idx = (ctx >> (12 - 4 * t)) & 0x1FFu;
                    const ull w2 = lds64(lut_lane + idx * 128u);
                    const int j = h * 4 + t;    // column pair within row
                    fma2(acc[tx][0], w2, x2[0][j]);
                    fma2(acc[tx][1], w2, x2[1][j]);
                    fma2(acc[tx][2], w2, x2[2][j]);
                    fma2(acc[tx][3], w2, x2[3][j]);
                }
            }
        }

        // collapse packed partials, then value-rotating warp reduction:
        // 32 sums over 32 lanes -> 1 sum per lane (62 shfl+add total).
        float v[32];
#pragma unroll
        for (int t = 0; t < 8; t++)
#pragma unroll
            for (int b = 0; b < 4; b++) v[t * 4 + b] = sum2(acc[t][b]);

#define ROUND(S, N) { _Pragma("unroll")                                   \
        for (int i = 0; i < (N) / 2; i++) {                               \
            const bool hi = (lane & (S)) != 0;                            \
            const float snd = hi ? v[i] : v[i + (N) / 2];                 \
            const float kp  = hi ? v[i + (N) / 2] : v[i];                 \
            v[i] = kp + __shfl_xor_sync(0xffffffffu, snd, (S));           \
        } }
        ROUND(1, 32) ROUND(2, 16) ROUND(4, 8) ROUND(8, 4) ROUND(16, 2)
#undef ROUND

        // lane l ends holding output index bitrev5(l) within this phase
        const int oi = ((lane & 1) << 4) | ((lane & 2) << 2) | (lane & 4)
                     | ((lane & 8) >> 2) | ((lane & 16) >> 4);
        red[warp * 64 + p2 * 32 + oi] = v[0];
    }

    __syncthreads();

    // cross-warp combine: 64 outputs (16 rows x 4 batches), 8 warps each
    if (tid < 64) {
        float s = 0.f;
#pragma unroll
        for (int w = 0; w < 8; w++) s += red[w * 64 + tid];
        const int r = tid >> 2;     // index j = tx*4+b, row = p2*8+tx = j>>2
        const int b = tid & 3;
        out[(size_t)b * OUTF + mo * 16 + r] = s;
    }
}

extern "C" void kernel_launch(void* const* d_in, const int* in_sizes, int n_in,
                              void* d_out, int out_size) {
    const float* inp  = (const float*)d_in[0];
    const int*   t1   = (const int*)d_in[1];
    const int*   t2   = (const int*)d_in[2];
    const float* tlut = (const float*)d_in[3];
    float*       out  = (float*)d_out;

    cudaFuncSetAttribute(tcq_kernel,
                         cudaFuncAttributeMaxDynamicSharedMemorySize,
                         SMEM_TOTAL);
    tcq_kernel<<<NBLK, THREADS, SMEM_TOTAL>>>(inp, t1, t2, tlut, out);
}